// round 15
// baseline (speedup 1.0000x reference)
#include <cuda_runtime.h>
#include <math.h>

// out[b,c,p,n,q] = sum_h C[n,h] * x[b,c,p,h,q]  for p<26,q<26 ; else 0.
// C (32x64) = (M32^3)^T[:, :26] @ (M64^3)[:26, :]   (host-computed in double)
//
// R13: persistent blocks (grid=444=148x3) + device tile queue (no wave tail);
// n-pair FMA2 packing (C const pairs used directly, 4 DUP2/k instead of 8);
// const-bank a-operand + swizzled double-buffered smem staging from R11.

struct CtParam { float ct[64][32]; };   // ct[h][n]

#define NTILES 1024
#define GRID   444

#define FMA2(d, a, b)   asm("fma.rn.f32x2 %0, %1, %2, %0;" : "+l"(d) : "l"(a), "l"(b))
#define DUP2(d, f)      asm("mov.b64 %0, {%1, %1};" : "=l"(d) : "f"(f))
#define UNPK2(lo, hi, s) asm("mov.b64 {%0, %1}, %2;" : "=f"(lo), "=f"(hi) : "l"(s))

__device__ unsigned int g_tile_ctr;

__global__ void reset_ctr_kernel() { g_tile_ctr = 0u; }

__global__ void __launch_bounds__(256, 3) spectral_pool_kernel(
    const float* __restrict__ x, float* __restrict__ out,
    const __grid_constant__ CtParam cp)
{
    __shared__ float4 sX[2][16][8][8];      // [buf][h][p][slot] : 32 KB
    __shared__ unsigned int sTile;

    const int tid = threadIdx.x;

    // ---- loader decomposition: 4 float4 per 16h-chunk ----
    const int ls   = tid & 7;               // q float4-slot 0..7
    const int lp   = (tid >> 3) & 7;        // p_local
    const int lh0  = tid >> 6;              // h = lh0 + 4j
    const int lss  = ls ^ ((lp & 1) << 2);  // XOR swizzle
    const bool lz  = (ls == 7);             // q 28..31 -> 0
    const bool lt  = (ls == 6);             // q 26,27 -> 0

    // ---- compute decomposition: warp = 8n x 8p x 16q ; thread = 8n x 4q ----
    const int w    = tid >> 5;
    const int nb   = w & 3;                 // n-block (n0 = nb*8)
    const int qh   = w >> 2;                // q-half
    const int lane = tid & 31;
    const int pl   = lane >> 2;             // p_local 0..7
    const int qg   = lane & 3;
    const int slot = (qh * 4 + qg) ^ ((pl & 1) << 2);
    const int n0   = nb * 8;

    // C rows as f32x2 n-pairs straight from the param constant bank (uniform)
    const ulonglong2* cU = reinterpret_cast<const ulonglong2*>(&cp.ct[0][0]);

    for (;;) {
        if (tid == 0) sTile = atomicAdd(&g_tile_ctr, 1u);
        __syncthreads();
        const unsigned int t = sTile;
        if (t >= NTILES) break;

        const int bc = t >> 2;
        const int pt = t & 3;
        const bool lpa = (pt * 8 + lp) < 26;
        const float* xb = x + (size_t)bc * 262144 + (size_t)(pt * 8 + lp) * 4096 + ls * 4;

        unsigned long long acc[4][4];       // [n-pair][q] f32x2
#pragma unroll
        for (int r = 0; r < 4; r++)
#pragma unroll
            for (int j = 0; j < 4; j++) acc[r][j] = 0ull;

        float4 v[4];

#define LOADCHUNK(kc) do {                                                     \
    _Pragma("unroll")                                                          \
    for (int j = 0; j < 4; j++) {                                              \
        v[j] = make_float4(0.f, 0.f, 0.f, 0.f);                                \
        if (!lz && lpa)                                                        \
            v[j] = __ldcs(reinterpret_cast<const float4*>(                     \
                xb + (size_t)((kc) * 16 + lh0 + 4 * j) * 64));                 \
        if (lt) { v[j].z = 0.f; v[j].w = 0.f; }                                \
    }                                                                          \
} while (0)

#define STORECHUNK(buf) do {                                                   \
    _Pragma("unroll")                                                          \
    for (int j = 0; j < 4; j++)                                                \
        sX[buf][lh0 + 4 * j][lp][lss] = v[j];                                  \
} while (0)

#define COMPUTE(buf, kc) do {                                                  \
    _Pragma("unroll")                                                          \
    for (int k = 0; k < 16; k++) {                                             \
        const int h = (kc) * 16 + k;                                           \
        ulonglong2 a0 = cU[h * 8 + nb * 2];      /* n-pairs 0,1  (uniform) */  \
        ulonglong2 a1 = cU[h * 8 + nb * 2 + 1];  /* n-pairs 2,3 */             \
        float4 bx = sX[buf][k][pl][slot];                                      \
        unsigned long long d0, d1, d2, d3;                                     \
        DUP2(d0, bx.x); DUP2(d1, bx.y); DUP2(d2, bx.z); DUP2(d3, bx.w);        \
        FMA2(acc[0][0], a0.x, d0); FMA2(acc[0][1], a0.x, d1);                  \
        FMA2(acc[0][2], a0.x, d2); FMA2(acc[0][3], a0.x, d3);                  \
        FMA2(acc[1][0], a0.y, d0); FMA2(acc[1][1], a0.y, d1);                  \
        FMA2(acc[1][2], a0.y, d2); FMA2(acc[1][3], a0.y, d3);                  \
        FMA2(acc[2][0], a1.x, d0); FMA2(acc[2][1], a1.x, d1);                  \
        FMA2(acc[2][2], a1.x, d2); FMA2(acc[2][3], a1.x, d3);                  \
        FMA2(acc[3][0], a1.y, d0); FMA2(acc[3][1], a1.y, d1);                  \
        FMA2(acc[3][2], a1.y, d2); FMA2(acc[3][3], a1.y, d3);                  \
    }                                                                          \
} while (0)

        LOADCHUNK(0); STORECHUNK(0); __syncthreads();
        LOADCHUNK(1); COMPUTE(0, 0); STORECHUNK(1); __syncthreads();
        LOADCHUNK(2); COMPUTE(1, 1); STORECHUNK(0); __syncthreads();
        LOADCHUNK(3); COMPUTE(0, 2); STORECHUNK(1); __syncthreads();
        COMPUTE(1, 3);

        // epilogue: unpack n-pairs -> per-n float4 rows, 8 x STG.128
        float* ob = out + (size_t)bc * 32768 + (size_t)(pt * 8 + pl) * 1024
                        + qh * 16 + qg * 4;
#pragma unroll
        for (int r = 0; r < 4; r++) {
            float e0, o0, e1, o1, e2, o2, e3, o3;
            UNPK2(e0, o0, acc[r][0]); UNPK2(e1, o1, acc[r][1]);
            UNPK2(e2, o2, acc[r][2]); UNPK2(e3, o3, acc[r][3]);
            *reinterpret_cast<float4*>(ob + (size_t)(n0 + 2 * r) * 32) =
                make_float4(e0, e1, e2, e3);
            *reinterpret_cast<float4*>(ob + (size_t)(n0 + 2 * r + 1) * 32) =
                make_float4(o0, o1, o2, o3);
        }
        // no sync needed here: next iteration's pop sync precedes any sX write
    }
}

// ---------------- host side ----------------

static void mm_d(const double* A, const double* B, double* C, int n)
{
    for (int i = 0; i < n; i++)
        for (int j = 0; j < n; j++) {
            double s = 0.0;
            for (int k = 0; k < n; k++) s += A[i * n + k] * B[k * n + j];
            C[i * n + j] = s;
        }
}

static void build_ct(CtParam* cp)
{
    static double M64[64 * 64], T64[64 * 64], P64[64 * 64];
    static double M32[32 * 32], T32[32 * 32], P32[32 * 32];

    const double PI = 3.14159265358979323846;
    for (int k = 0; k < 64; k++)
        for (int n = 0; n < 64; n++) {
            double v = sqrt(2.0 / 64.0) * cos(PI * (2.0 * n + 1.0) * k / 128.0);
            if (k == 0) v = 1.0 / 8.0;
            M64[k * 64 + n] = v;
        }
    for (int k = 0; k < 32; k++)
        for (int n = 0; n < 32; n++) {
            double v = sqrt(2.0 / 32.0) * cos(PI * (2.0 * n + 1.0) * k / 64.0);
            if (k == 0) v = 1.0 / sqrt(32.0);
            M32[k * 32 + n] = v;
        }

    mm_d(M64, M64, T64, 64);
    mm_d(T64, M64, P64, 64);     // M64^3
    mm_d(M32, M32, T32, 32);
    mm_d(T32, M32, P32, 32);     // M32^3

    for (int n = 0; n < 32; n++)
        for (int h = 0; h < 64; h++) {
            double s = 0.0;
            for (int k = 0; k < 26; k++)
                s += P32[k * 32 + n] * P64[k * 64 + h];
            cp->ct[h][n] = (float)s;
        }
}

extern "C" void kernel_launch(void* const* d_in, const int* in_sizes, int n_in,
                              void* d_out, int out_size)
{
    (void)in_sizes; (void)n_in; (void)out_size;
    const float* x = (const float*)d_in[0];
    float* out = (float*)d_out;

    static CtParam cp;
    build_ct(&cp);

    reset_ctr_kernel<<<1, 1>>>();
    spectral_pool_kernel<<<GRID, 256>>>(x, out, cp);
}